// round 17
// baseline (speedup 1.0000x reference)
#include <cuda_runtime.h>
#include <cuda_bf16.h>
#include <cstdint>
#include <cstddef>

#define T_STEPS 2048
#define OFF 8
#define NTHR 288

typedef unsigned long long ull;

// ---------------------------------------------------------------------------
// Device-global tagged history rings (+1 slot so prestage reads stay in
// bounds): word = {hi32: tag, lo32: f32 h}. slot = t + OFF, tag = slot + 1.
// ---------------------------------------------------------------------------
__device__ ull g_hist0[(T_STEPS + OFF + 1) * 128];
__device__ ull g_hist1[(T_STEPS + OFF + 1) * 128];
__device__ ull g_hist2[(T_STEPS + OFF + 1) * 128];
__device__ ull g_hist3[(T_STEPS + OFF + 1) * 256];
__device__ float g_zx[(size_t)T_STEPS * 512];   // Wih0@x + bih0 + bhh0

// ---------------------------------------------------------------------------
__device__ __forceinline__ ull ldr(const ull* p) {
    ull v;
    asm volatile("ld.relaxed.gpu.global.u64 %0, [%1];" : "=l"(v) : "l"(p) : "memory");
    return v;
}
__device__ __forceinline__ void str(ull* p, ull v) {
    asm volatile("st.relaxed.gpu.global.u64 [%0], %1;" :: "l"(p), "l"(v) : "memory");
}
__device__ __forceinline__ ull pack_hv(float h, unsigned tag) {
    return ((ull)tag << 32) | (ull)__float_as_uint(h);
}
// fast activations: single-MUFU tanh; sigmoid via tanh identity
__device__ __forceinline__ float tanh_ap(float x) {
    float y;
    asm("tanh.approx.f32 %0, %1;" : "=f"(y) : "f"(x));
    return y;
}
__device__ __forceinline__ float sig_ap(float x) {
    return fmaf(0.5f, tanh_ap(0.5f * x), 0.5f);
}
__device__ __forceinline__ uint32_t smem_u32(const void* p) {
    uint32_t a;
    asm("{ .reg .u64 t; cvta.to.shared.u64 t, %1; cvt.u32.u64 %0, t; }"
        : "=r"(a) : "l"(p));
    return a;
}
__device__ __forceinline__ ull lds_vol(uint32_t a) {
    ull v;
    asm volatile("ld.volatile.shared.u64 %0, [%1];" : "=l"(v) : "r"(a) : "memory");
    return v;
}
__device__ __forceinline__ void sts_cluster(uint32_t a, ull v) {
    asm volatile("st.relaxed.cluster.shared::cluster.u64 [%0], %1;"
                 :: "r"(a), "l"(v) : "memory");
}
__device__ __forceinline__ void cluster_sync_() {
    asm volatile("barrier.cluster.arrive.aligned;" ::: "memory");
    asm volatile("barrier.cluster.wait.aligned;" ::: "memory");
}
__device__ __forceinline__ ull fma2_(ull a, ull b, ull c) {
    ull d;
    asm("fma.rn.f32x2 %0, %1, %2, %3;" : "=l"(d) : "l"(a), "l"(b), "l"(c));
    return d;
}

// ---------------------------------------------------------------------------
// Init: zero tags (incl. spare slot), seed initial h. Every replay.
// ---------------------------------------------------------------------------
__device__ void init_one(ull* hist, int DOUT, int DIL, const float* h0,
                         int gid, int gs) {
    int N = (T_STEPS + OFF + 1) * DOUT;
    for (int i = gid; i < N; i += gs) {
        int s = i / DOUT;
        int j = i - s * DOUT;
        ull v = 0ull;
        if (s >= OFF - DIL && s < OFF)
            v = pack_hv(h0[(s - (OFF - DIL)) * DOUT + j], (unsigned)(s + 1));
        hist[i] = v;
    }
}

__global__ void init_hist_kernel(const float* __restrict__ h00,
                                 const float* __restrict__ h01,
                                 const float* __restrict__ h02,
                                 const float* __restrict__ h03) {
    int gid = blockIdx.x * blockDim.x + threadIdx.x;
    int gs = gridDim.x * blockDim.x;
    init_one(g_hist0, 128, 1, h00, gid, gs);
    init_one(g_hist1, 128, 2, h01, gid, gs);
    init_one(g_hist2, 128, 4, h02, gid, gs);
    init_one(g_hist3, 256, 8, h03, gid, gs);
}

// ---------------------------------------------------------------------------
// Layer-0 input projection GEMM: g_zx[t][r] = Wih0[r]·x[t] + bih0[r] + bhh0[r]
// ---------------------------------------------------------------------------
__global__ void __launch_bounds__(256) xproj_kernel(const float* __restrict__ x,
                                                    const float* __restrict__ W,
                                                    const float* __restrict__ b1,
                                                    const float* __restrict__ b2) {
    __shared__ float Xs[16][129];
    __shared__ float Ws[16][65];
    const int tid = threadIdx.x;
    const int m0 = blockIdx.x * 128;
    const int n0 = blockIdx.y * 64;
    const int tm = (tid >> 4) * 8;
    const int tn = (tid & 15) * 4;

    float acc[8][4];
#pragma unroll
    for (int i = 0; i < 8; i++)
#pragma unroll
        for (int j = 0; j < 4; j++) acc[i][j] = 0.0f;

    for (int k0 = 0; k0 < 256; k0 += 16) {
#pragma unroll
        for (int i = 0; i < 2; i++) {
            int f = tid + i * 256;
            int m = f >> 2;
            int kq = (f & 3) * 4;
            float4 v = *(const float4*)(x + (size_t)(m0 + m) * 256 + k0 + kq);
            Xs[kq + 0][m] = v.x; Xs[kq + 1][m] = v.y;
            Xs[kq + 2][m] = v.z; Xs[kq + 3][m] = v.w;
        }
        {
            int r = tid >> 2;
            int kq = (tid & 3) * 4;
            float4 v = *(const float4*)(W + (size_t)(n0 + r) * 256 + k0 + kq);
            Ws[kq + 0][r] = v.x; Ws[kq + 1][r] = v.y;
            Ws[kq + 2][r] = v.z; Ws[kq + 3][r] = v.w;
        }
        __syncthreads();
#pragma unroll
        for (int k = 0; k < 16; k++) {
            float rm[8], rn[4];
#pragma unroll
            for (int i = 0; i < 8; i++) rm[i] = Xs[k][tm + i];
#pragma unroll
            for (int j = 0; j < 4; j++) rn[j] = Ws[k][tn + j];
#pragma unroll
            for (int i = 0; i < 8; i++)
#pragma unroll
                for (int j = 0; j < 4; j++)
                    acc[i][j] = fmaf(rm[i], rn[j], acc[i][j]);
        }
        __syncthreads();
    }
#pragma unroll
    for (int i = 0; i < 8; i++)
#pragma unroll
        for (int j = 0; j < 4; j++) {
            int r = n0 + tn + j;
            g_zx[(size_t)(m0 + tm + i) * 512 + r] = acc[i][j] + b1[r] + b2[r];
        }
}

// ---------------------------------------------------------------------------
// Layer 0: 2-CTA cluster, split-GEMV with DSMEM-transit overlap, fused fast
// gates, DEDICATED POLL WARP (warp 8). Warps 0-7 compute; warp 8 polls the
// peer ring right after bar1 (reaches the poll ~140 cyc earlier than a
// compute warp could), writes the act peer half, and carries no FMA work so
// no compute warp straggles at bar2.
// ---------------------------------------------------------------------------
__device__ void run_layer0_pair(int rank,
                                const float* __restrict__ Whh,
                                const float* __restrict__ c0,
                                const float* __restrict__ h0,
                                ull* __restrict__ ring,   /* smem [2][64] */
                                float* __restrict__ act   /* smem [128], 16B aligned */) {
    const int tid  = threadIdx.x;
    const int lane = tid & 31;
    const int w    = tid >> 5;          // 0..8
    const int x    = lane & 7;
    const int c    = lane >> 3;
    const int e    = 64 * rank + 8 * w + x;   // valid for w<8

    ull wo[4][8], wp[4][8];
    const int ownb  = 64 * rank + 16 * c;
    const int peerb = 64 * (1 - rank) + 16 * c;
    if (w < 8) {
#pragma unroll
        for (int g = 0; g < 4; g++) {
            const float* row = Whh + (size_t)(g * 128 + e) * 128;
#pragma unroll
            for (int k = 0; k < 8; k++) {
                wo[g][k] = (ull)__float_as_uint(row[ownb + 2 * k]) |
                           ((ull)__float_as_uint(row[ownb + 2 * k + 1]) << 32);
                wp[g][k] = (ull)__float_as_uint(row[peerb + 2 * k]) |
                           ((ull)__float_as_uint(row[peerb + 2 * k + 1]) << 32);
            }
        }
    }

    if (tid < 128) ring[tid] = 0ull;
    if (tid < 128) act[tid] = h0[tid];

    float creg = 0.0f;
    uint32_t peer_addr = 0;
    if (w < 8 && lane < 8) {
        creg = c0[e];
        uint32_t local = smem_u32(&ring[8 * w + x]);
        asm("mapa.shared::cluster.u32 %0, %1, %2;"
            : "=r"(peer_addr) : "r"(local), "r"(1 - rank));
    }
    const uint32_t ring_base = smem_u32(ring);
    __syncthreads();
    cluster_sync_();

    const ull* hv = (const ull*)act;
    const int ou = ownb >> 1;
    const int pu = peerb >> 1;

    for (int t = 0; t < T_STEPS; t++) {
        float zx0 = 0.f, zx1 = 0.f, zx2 = 0.f, zx3 = 0.f;
        if (w < 8 && lane < 8) {
            const float* zp = &g_zx[(size_t)t * 512 + e];
            zx0 = __ldg(zp);       zx1 = __ldg(zp + 128);
            zx2 = __ldg(zp + 256); zx3 = __ldg(zp + 384);
        }

        __syncthreads();              // bar1: act own half (t-1) visible

        ull a0 = 0, a1 = 0, a2 = 0, a3 = 0;
        if (w < 8) {
            // own-half FMA (overlaps the peer's DSMEM transit)
            ull h[8];
#pragma unroll
            for (int k = 0; k < 4; k++)
                ((ulonglong2*)h)[k] = ((const ulonglong2*)(hv + ou))[k];
#pragma unroll
            for (int k = 0; k < 8; k++) {
                a0 = fma2_(wo[0][k], h[k], a0);
                a1 = fma2_(wo[1][k], h[k], a1);
                a2 = fma2_(wo[2][k], h[k], a2);
                a3 = fma2_(wo[3][k], h[k], a3);
            }
        } else if (t > 0) {
            // dedicated poll warp: peer half, slot (t-1)&1, tag t+1
            const uint32_t sb = ring_base + (((t - 1) & 1) ? 512u : 0u);
            const unsigned ex = (unsigned)(t + 1);
            ull v0 = lds_vol(sb + lane * 8);
            ull v1 = lds_vol(sb + (lane + 32) * 8);
            while ((unsigned)(v0 >> 32) != ex) v0 = lds_vol(sb + lane * 8);
            while ((unsigned)(v1 >> 32) != ex) v1 = lds_vol(sb + (lane + 32) * 8);
            act[64 * (1 - rank) + lane]      = __uint_as_float((unsigned)v0);
            act[64 * (1 - rank) + lane + 32] = __uint_as_float((unsigned)v1);
        }

        __syncthreads();              // bar2: act peer half (t-1) visible

        if (w < 8) {
            {
                ull h[8];
#pragma unroll
                for (int k = 0; k < 4; k++)
                    ((ulonglong2*)h)[k] = ((const ulonglong2*)(hv + pu))[k];
#pragma unroll
                for (int k = 0; k < 8; k++) {
                    a0 = fma2_(wp[0][k], h[k], a0);
                    a1 = fma2_(wp[1][k], h[k], a1);
                    a2 = fma2_(wp[2][k], h[k], a2);
                    a3 = fma2_(wp[3][k], h[k], a3);
                }
            }

            float s0 = __uint_as_float((unsigned)a0) + __uint_as_float((unsigned)(a0 >> 32));
            float s1 = __uint_as_float((unsigned)a1) + __uint_as_float((unsigned)(a1 >> 32));
            float s2 = __uint_as_float((unsigned)a2) + __uint_as_float((unsigned)(a2 >> 32));
            float s3 = __uint_as_float((unsigned)a3) + __uint_as_float((unsigned)(a3 >> 32));
            s0 += __shfl_xor_sync(0xffffffffu, s0, 8);
            s1 += __shfl_xor_sync(0xffffffffu, s1, 8);
            s2 += __shfl_xor_sync(0xffffffffu, s2, 8);
            s3 += __shfl_xor_sync(0xffffffffu, s3, 8);
            s0 += __shfl_xor_sync(0xffffffffu, s0, 16);
            s1 += __shfl_xor_sync(0xffffffffu, s1, 16);
            s2 += __shfl_xor_sync(0xffffffffu, s2, 16);
            s3 += __shfl_xor_sync(0xffffffffu, s3, 16);

            if (lane < 8) {
                float ig = sig_ap(s0 + zx0);
                float fg = sig_ap(s1 + zx1);
                float gg = tanh_ap(s2 + zx2);
                float og = sig_ap(s3 + zx3);
                float c2 = fg * creg + ig * gg;
                creg = c2;
                float h2 = og * tanh_ap(c2);

                // publish FIRST: start the 215-cyc transit ASAP
                if (t < T_STEPS - 1)
                    sts_cluster(peer_addr + ((t & 1) ? 512u : 0u),
                                pack_hv(h2, (unsigned)(t + 2)));
                act[e] = h2;
                str(g_hist0 + (size_t)(t + OFF) * 128 + e,
                    pack_hv(h2, (unsigned)(t + OFF + 1)));
            }
        }
    }

    cluster_sync_();                  // exit safety: peer stores consumed
}

// ---------------------------------------------------------------------------
// Upper layers (1..3): prestaged coop staging (288 threads; warp 8 helps
// stage and matches barriers, skips GEMV). One barrier per step.
// ---------------------------------------------------------------------------
template <int DIN, int DOUT, int G, int DILN, int MODE>
__device__ void run_layer_coop(int cta,
                               const float* __restrict__ Wih,
                               const float* __restrict__ Whh,
                               const float* __restrict__ bih,
                               const float* __restrict__ bhh,
                               const float* __restrict__ c0,
                               const ull* __restrict__ hin,
                               ull* __restrict__ hown,
                               float* __restrict__ out,
                               float* __restrict__ act /* [2][COLS] */) {
    constexpr int CHUNK = DOUT / G;       // 8
    constexpr int COLS  = DIN + DOUT;     // 256 or 384
    constexpr int CPL   = COLS / 32;      // 8 or 12
    static_assert(CHUNK == 8, "8 warps x 1 elem");

    const int tid  = threadIdx.x;
    const int lane = tid & 31;
    const int w    = tid >> 5;            // 0..8
    const int e    = cta * CHUNK + w;     // valid for w<8

    float wreg[4][CPL];
    if (w < 8) {
#pragma unroll
        for (int g = 0; g < 4; g++) {
            int zr = g * DOUT + e;
#pragma unroll
            for (int k = 0; k < CPL; k++) {
                int j = lane + 32 * k;
                wreg[g][k] = (j < DIN) ? Wih[(size_t)zr * DIN + j]
                                       : Whh[(size_t)zr * DOUT + (j - DIN)];
            }
        }
    }
    float b0 = 0, b1 = 0, b2 = 0, b3 = 0;
    float creg[DILN];
    if (w < 8 && lane == 0) {
        b0 = bih[0 * DOUT + e] + bhh[0 * DOUT + e];
        b1 = bih[1 * DOUT + e] + bhh[1 * DOUT + e];
        b2 = bih[2 * DOUT + e] + bhh[2 * DOUT + e];
        b3 = bih[3 * DOUT + e] + bhh[3 * DOUT + e];
#pragma unroll
        for (int k = 0; k < DILN; k++) creg[k] = c0[k * DOUT + e];
    }

    // ---- staging slots: idx0 = tid, idx1 = tid + NTHR ----
    const int idx0 = tid;
    const int idx1 = tid + NTHR;
    const bool h0v = (idx0 < COLS);
    const bool h1v = (idx1 < COLS);
    const ull* q0 = nullptr; unsigned ex0 = 0; int inc0 = 0;
    const ull* q1 = nullptr; unsigned ex1 = 0; int inc1 = 0;
    if (h0v) {
        if (idx0 < DIN) { q0 = hin + (size_t)OFF * DIN + idx0;
                          ex0 = OFF + 1; inc0 = DIN; }
        else            { q0 = hown + (size_t)(OFF - DILN) * DOUT + (idx0 - DIN);
                          ex0 = OFF - DILN + 1; inc0 = DOUT; }
    }
    if (h1v) {
        if (idx1 < DIN) { q1 = hin + (size_t)OFF * DIN + idx1;
                          ex1 = OFF + 1; inc1 = DIN; }
        else            { q1 = hown + (size_t)(OFF - DILN) * DOUT + (idx1 - DIN);
                          ex1 = OFF - DILN + 1; inc1 = DOUT; }
    }
    ull v0 = h0v ? ldr(q0) : 0ull;
    ull v1 = h1v ? ldr(q1) : 0ull;

    for (int tb = 0; tb < T_STEPS; tb += DILN) {
#pragma unroll
        for (int kk = 0; kk < DILN; kk++) {
            const int t = tb + kk;
            float* buf = act + (t & 1) * COLS;
            if (h0v) {
                while ((unsigned)(v0 >> 32) != ex0) v0 = ldr(q0);
                buf[idx0] = __uint_as_float((unsigned)v0);
            }
            if (h1v) {
                while ((unsigned)(v1 >> 32) != ex1) v1 = ldr(q1);
                buf[idx1] = __uint_as_float((unsigned)v1);
            }
            __syncthreads();

            // prestage step t+1 — latency hides under compute below
            if (h0v) { q0 += inc0; ex0 += 1; v0 = ldr(q0); }
            if (h1v) { q1 += inc1; ex1 += 1; v1 = ldr(q1); }

            if (w < 8) {
                float a0 = 0, a1 = 0, a2 = 0, a3 = 0;
#pragma unroll
                for (int k = 0; k < CPL; k++) {
                    float a = buf[lane + 32 * k];
                    a0 = fmaf(wreg[0][k], a, a0);
                    a1 = fmaf(wreg[1][k], a, a1);
                    a2 = fmaf(wreg[2][k], a, a2);
                    a3 = fmaf(wreg[3][k], a, a3);
                }
#pragma unroll
                for (int d = 16; d > 0; d >>= 1) {
                    a0 += __shfl_xor_sync(0xffffffffu, a0, d);
                    a1 += __shfl_xor_sync(0xffffffffu, a1, d);
                    a2 += __shfl_xor_sync(0xffffffffu, a2, d);
                    a3 += __shfl_xor_sync(0xffffffffu, a3, d);
                }
                if (lane == 0) {
                    float ig = sig_ap(a0 + b0);
                    float fg = sig_ap(a1 + b1);
                    float gg = tanh_ap(a2 + b2);
                    float og = sig_ap(a3 + b3);
                    float c2 = fg * creg[kk] + ig * gg;
                    creg[kk] = c2;
                    float h2 = og * tanh_ap(c2);
                    str(hown + (size_t)(t + OFF) * DOUT + e,
                        pack_hv(h2, (unsigned)(t + OFF + 1)));
                    if (MODE == 2) out[(size_t)t * 256 + e] = h2;
                }
            }
        }
    }
}

// ---------------------------------------------------------------------------
struct DP {
    const float *Whh0, *h00, *c00;
    const float *Wih1, *Whh1, *bih1, *bhh1, *c01;
    const float *Wih2, *Whh2, *bih2, *bhh2, *c02;
    const float *Wih3, *Whh3, *bih3, *bhh3, *c03;
    float* out;
};

// 66 CTAs, cluster 2: {0,1}=L0 pair; [2,18)=L1; [18,34)=L2; [34,66)=L3.
__global__ void __launch_bounds__(NTHR, 1) __cluster_dims__(2, 1, 1)
drnn_kernel(DP p) {
    __shared__ ull ring[2 * 64];
    __shared__ __align__(16) float act0[128];
    __shared__ float act[2 * 384];
    int b = blockIdx.x;
    if (b < 2) {
        run_layer0_pair(b, p.Whh0, p.c00, p.h00, ring, act0);
    } else if (b < 18) {
        run_layer_coop<128, 128, 16, 2, 0>(b - 2, p.Wih1, p.Whh1, p.bih1,
                                           p.bhh1, p.c01, g_hist0, g_hist1,
                                           nullptr, act);
    } else if (b < 34) {
        run_layer_coop<128, 128, 16, 4, 0>(b - 18, p.Wih2, p.Whh2, p.bih2,
                                           p.bhh2, p.c02, g_hist1, g_hist2,
                                           nullptr, act);
    } else {
        run_layer_coop<128, 256, 32, 8, 2>(b - 34, p.Wih3, p.Whh3, p.bih3,
                                           p.bhh3, p.c03, g_hist2, g_hist3,
                                           p.out, act);
    }
}

// ---------------------------------------------------------------------------
extern "C" void kernel_launch(void* const* d_in, const int* in_sizes, int n_in,
                              void* d_out, int out_size) {
    // detect interleaved (x,[W,U,bi,bh,h0,c0]*4) vs grouped (x, W*16, states*8)
    int iW[4], iU[4], ibi[4], ibh[4], ih[4], ic[4];
    if (in_sizes[5] == 128) {            // interleaved
        for (int i = 0; i < 4; i++) {
            int base = 1 + i * 6;
            iW[i] = base; iU[i] = base + 1; ibi[i] = base + 2; ibh[i] = base + 3;
            ih[i] = base + 4; ic[i] = base + 5;
        }
    } else {                             // grouped
        for (int i = 0; i < 4; i++) {
            iW[i] = 1 + 4 * i; iU[i] = 2 + 4 * i;
            ibi[i] = 3 + 4 * i; ibh[i] = 4 + 4 * i;
            ih[i] = 17 + 2 * i; ic[i] = 18 + 2 * i;
        }
    }

    const float* x = (const float*)d_in[0];

    init_hist_kernel<<<256, 256>>>((const float*)d_in[ih[0]],
                                   (const float*)d_in[ih[1]],
                                   (const float*)d_in[ih[2]],
                                   (const float*)d_in[ih[3]]);

    dim3 g(16, 8);
    xproj_kernel<<<g, 256>>>(x, (const float*)d_in[iW[0]],
                             (const float*)d_in[ibi[0]],
                             (const float*)d_in[ibh[0]]);

    DP p;
    p.Whh0 = (const float*)d_in[iU[0]];
    p.h00  = (const float*)d_in[ih[0]];
    p.c00  = (const float*)d_in[ic[0]];
    p.Wih1 = (const float*)d_in[iW[1]]; p.Whh1 = (const float*)d_in[iU[1]];
    p.bih1 = (const float*)d_in[ibi[1]]; p.bhh1 = (const float*)d_in[ibh[1]];
    p.c01  = (const float*)d_in[ic[1]];
    p.Wih2 = (const float*)d_in[iW[2]]; p.Whh2 = (const float*)d_in[iU[2]];
    p.bih2 = (const float*)d_in[ibi[2]]; p.bhh2 = (const float*)d_in[ibh[2]];
    p.c02  = (const float*)d_in[ic[2]];
    p.Wih3 = (const float*)d_in[iW[3]]; p.Whh3 = (const float*)d_in[iU[3]];
    p.bih3 = (const float*)d_in[ibi[3]]; p.bhh3 = (const float*)d_in[ibh[3]];
    p.c03  = (const float*)d_in[ic[3]];
    p.out  = (float*)d_out;

    drnn_kernel<<<66, NTHR>>>(p);
}